// round 14
// baseline (speedup 1.0000x reference)
#include <cuda_runtime.h>
#include <cuda_fp16.h>
#include <cstdint>

#define N_TOK 4096
#define NH 12
#define HD 64
#define DMODEL 768
#define QK_SCALE 0.125f
#define LOG2E 1.4426950408889634f
#define NSPLIT 3

// Scratch (device globals: allocation-free per harness rules)
__device__ __half g_qkvh[(size_t)N_TOK * 3 * DMODEL]; // fp16 qkv [n][3D] canonical
__device__ __half g_hs[(size_t)N_TOK * DMODEL];        // fp16 hidden_states, word-permuted k
__device__ __half g_w1t[(size_t)3 * DMODEL * DMODEL];  // fp16 qkv_w^T [n][k], word-permuted k
__device__ __half g_w2t[(size_t)DMODEL * DMODEL];      // fp16 proj_w^T [n][k], word-permuted k
__device__ __half g_q[(size_t)NH * N_TOK * HD];        // [h][n][d-perm], *scale*log2e
__device__ __half g_k[(size_t)NH * N_TOK * HD];        // [h][n][d-perm]
__device__ __half g_vt[(size_t)NH * HD * N_TOK];       // [h][d][key-perm] V^T
__device__ __half g_att[(size_t)N_TOK * DMODEL];       // attn out [n][h*HD+d], word-permuted
// split-K partials + combine counters (mod-NSPLIT protocol, never reset)
__device__ float g_po[(size_t)NSPLIT * NH * N_TOK * HD];
__device__ float g_pm[(size_t)NSPLIT * NH * N_TOK];
__device__ float g_pl[(size_t)NSPLIT * NH * N_TOK];
__device__ int   g_ctr[(N_TOK / 256) * NH];

// ---------------------------------------------------------------------------
// helpers
// ---------------------------------------------------------------------------
__device__ __forceinline__ float ex2(float x) {
    float y;
    asm("ex2.approx.f32 %0, %1;" : "=f"(y) : "f"(x));
    return y;
}
__device__ __forceinline__ void mma_fp16(float& c0, float& c1, float& c2, float& c3,
                                         uint32_t a0, uint32_t a1, uint32_t a2, uint32_t a3,
                                         uint32_t b0, uint32_t b1) {
    asm volatile(
        "mma.sync.aligned.m16n8k16.row.col.f32.f16.f16.f32 "
        "{%0,%1,%2,%3}, {%4,%5,%6,%7}, {%8,%9}, {%0,%1,%2,%3};\n"
        : "+f"(c0), "+f"(c1), "+f"(c2), "+f"(c3)
        : "r"(a0), "r"(a1), "r"(a2), "r"(a3), "r"(b0), "r"(b1));
}
__device__ __forceinline__ void cp16(uint32_t dst, const void* src) {
    asm volatile("cp.async.cg.shared.global [%0], [%1], 16;" :: "r"(dst), "l"(src));
}
#define CP_COMMIT() asm volatile("cp.async.commit_group;")
#define CP_WAIT(n)  asm volatile("cp.async.wait_group %0;" :: "n"(n))

// pair-interleave permutation on 32-bit words within each 8-word group
__device__ __forceinline__ int wperm(int w) {
    int r = w & 7;
    return (w & ~7) | ((r < 4) ? (2 * r) : (2 * (r - 4) + 1));
}
__device__ __forceinline__ uint32_t pack2(float lo, float hi) {
    __half2 h = __floats2half2_rn(lo, hi);
    return *reinterpret_cast<uint32_t*>(&h);
}

// ---------------------------------------------------------------------------
// hs -> fp16, word-permuted k
// ---------------------------------------------------------------------------
__global__ void __launch_bounds__(256) convert_hs(const float* __restrict__ hs)
{
    int i = blockIdx.x * 256 + threadIdx.x;        // word index
    if (i >= N_TOK * DMODEL / 2) return;
    int row = i / (DMODEL / 2);
    int w = i % (DMODEL / 2);
    float2 v = *(const float2*)(hs + (size_t)row * DMODEL + w * 2);
    ((__half2*)g_hs)[(size_t)row * (DMODEL / 2) + wperm(w)] = __floats2half2_rn(v.x, v.y);
}

// ---------------------------------------------------------------------------
// W[K][N] -> WT[n][k] fp16, word-permuted k. 64x64 tiles.
// ---------------------------------------------------------------------------
__global__ void __launch_bounds__(256) transpose_w(const float* __restrict__ W,
                                                   __half* __restrict__ WT,
                                                   int K, int N)
{
    __shared__ float sm[64][65];
    const int n0 = blockIdx.x * 64, k0 = blockIdx.y * 64;
    const int tid = threadIdx.x;
#pragma unroll
    for (int i = 0; i < 16; i++) {
        int id = tid + i * 256;
        int kl = id >> 6, nl = id & 63;
        sm[kl][nl] = W[(size_t)(k0 + kl) * N + n0 + nl];
    }
    __syncthreads();
#pragma unroll
    for (int i = 0; i < 8; i++) {
        int id = tid + i * 256;
        int nl = id >> 5, wl = id & 31;
        int kl = wl * 2;
        __half2 v = __floats2half2_rn(sm[kl][nl], sm[kl + 1][nl]);
        int Wg = (k0 >> 1) + wl;
        ((__half2*)WT)[(size_t)(n0 + nl) * (K >> 1) + wperm(Wg)] = v;
    }
}

// ---------------------------------------------------------------------------
// fp16 GEMM: C[M,Nc] = A[M,K] @ BT[Nc,K]^T + bias.
// A,BT fp16 word-permuted k. 128x128x64 tiles, 256 thr, 2 CTA/SM, cp.async 2-buf.
// HALF_OUT: C stored as fp16 (canonical), else fp32.
// ---------------------------------------------------------------------------
#define AW 40                     // word stride (== 8 mod 32 -> conflict-free)
#define ABUF (128 * AW)
#define GEMM_SMEM (4 * ABUF * 4)

template <int HALF_OUT>
__global__ void __launch_bounds__(256, 2) gemm_fp16(
    const __half* __restrict__ A, const __half* __restrict__ BT,
    const float* __restrict__ bias, void* __restrict__ Cv,
    int M, int Nc, int K)
{
    extern __shared__ uint32_t smg[];
    uint32_t* As = smg;                 // [2][128][AW]
    uint32_t* Bs = smg + 2 * ABUF;      // [2][128][AW]

    const int tid = threadIdx.x;
    const int lane = tid & 31;
    const int w = tid >> 5;
    const int wm = w >> 2, wn = w & 3;
    const int q4 = lane & 3;
    const int bx = blockIdx.x, by = blockIdx.y;

    const __half* Ag = A + (size_t)(by * 128) * K;
    const __half* Bg = BT + (size_t)(bx * 128) * K;

    const uint32_t as_u = (uint32_t)__cvta_generic_to_shared(As);
    const uint32_t bs_u = (uint32_t)__cvta_generic_to_shared(Bs);

    float acc[4][4][4];
#pragma unroll
    for (int mt = 0; mt < 4; mt++)
#pragma unroll
        for (int nt = 0; nt < 4; nt++)
#pragma unroll
            for (int c = 0; c < 4; c++) acc[mt][nt][c] = 0.f;

    const int NC = K / 64;

#pragma unroll
    for (int i = 0; i < 4; i++) {
        int id = tid + i * 256;
        int r = id >> 3, c8 = (id & 7) * 8;
        cp16(as_u + (uint32_t)(r * AW + (id & 7) * 4) * 4, Ag + (size_t)r * K + c8);
        cp16(bs_u + (uint32_t)(r * AW + (id & 7) * 4) * 4, Bg + (size_t)r * K + c8);
    }
    CP_COMMIT();

    for (int ch = 0; ch < NC; ch++) {
        if (ch + 1 < NC) {
            int k0 = (ch + 1) * 64;
            int buf = (ch + 1) & 1;
#pragma unroll
            for (int i = 0; i < 4; i++) {
                int id = tid + i * 256;
                int r = id >> 3, c8 = (id & 7) * 8;
                cp16(as_u + (uint32_t)(buf * ABUF + r * AW + (id & 7) * 4) * 4,
                     Ag + (size_t)r * K + k0 + c8);
                cp16(bs_u + (uint32_t)(buf * ABUF + r * AW + (id & 7) * 4) * 4,
                     Bg + (size_t)r * K + k0 + c8);
            }
        }
        CP_COMMIT();
        CP_WAIT(1);
        __syncthreads();

        const uint32_t* Ab = As + (ch & 1) * ABUF;
        const uint32_t* Bb = Bs + (ch & 1) * ABUF;

#pragma unroll
        for (int ks = 0; ks < 4; ks++) {
            const int wc = ks * 8 + 2 * q4;
            uint2 a[4][2];
#pragma unroll
            for (int mt = 0; mt < 4; mt++) {
                int r = wm * 64 + mt * 16 + (lane >> 2);
                a[mt][0] = *(const uint2*)&Ab[r * AW + wc];
                a[mt][1] = *(const uint2*)&Ab[(r + 8) * AW + wc];
            }
            uint2 b[4];
#pragma unroll
            for (int nt = 0; nt < 4; nt++) {
                int n = wn * 32 + nt * 8 + (lane >> 2);
                b[nt] = *(const uint2*)&Bb[n * AW + wc];
            }
#pragma unroll
            for (int mt = 0; mt < 4; mt++)
#pragma unroll
                for (int nt = 0; nt < 4; nt++)
                    mma_fp16(acc[mt][nt][0], acc[mt][nt][1], acc[mt][nt][2], acc[mt][nt][3],
                             a[mt][0].x, a[mt][1].x, a[mt][0].y, a[mt][1].y,
                             b[nt].x, b[nt].y);
        }
        __syncthreads();
    }

#pragma unroll
    for (int mt = 0; mt < 4; mt++) {
#pragma unroll
        for (int nt = 0; nt < 4; nt++) {
            int r = by * 128 + wm * 64 + mt * 16 + (lane >> 2);
            int cn = bx * 128 + wn * 32 + nt * 8 + 2 * q4;
            float b0 = bias[cn], b1 = bias[cn + 1];
            if (HALF_OUT) {
                __half* C = (__half*)Cv;
                *(__half2*)(C + (size_t)r * Nc + cn) =
                    __floats2half2_rn(acc[mt][nt][0] + b0, acc[mt][nt][1] + b1);
                *(__half2*)(C + (size_t)(r + 8) * Nc + cn) =
                    __floats2half2_rn(acc[mt][nt][2] + b0, acc[mt][nt][3] + b1);
            } else {
                float* C = (float*)Cv;
                *(float2*)(C + (size_t)r * Nc + cn) =
                    make_float2(acc[mt][nt][0] + b0, acc[mt][nt][1] + b1);
                *(float2*)(C + (size_t)(r + 8) * Nc + cn) =
                    make_float2(acc[mt][nt][2] + b0, acc[mt][nt][3] + b1);
            }
        }
    }
}

// ---------------------------------------------------------------------------
// Fused post-QKV: RoPE+scale+split q/k (word-permuted) AND V transpose.
// ---------------------------------------------------------------------------
#define ROPE_BLOCKS (N_TOK * NH * 32 / 256)   // 6144
#define VT_BLOCKS ((N_TOK / 64) * NH)         // 768

__global__ void __launch_bounds__(256) qkv_post(const float* __restrict__ cosp,
                                                const float* __restrict__ sinp)
{
    __shared__ __half smv[64][72];
    const int bx = blockIdx.x;
    const int tid = threadIdx.x;

    if (bx < ROPE_BLOCKS) {
        int idx = bx * 256 + tid;
        int w = idx & 31;
        int h = (idx >> 5) % NH;
        int n = idx / (NH * 32);
        int d0 = 2 * w, d1 = 2 * w + 1;

        float c0 = cosp[n * HD + d0], c1 = cosp[n * HD + d1];
        float s0 = sinp[n * HD + d0], s1 = sinp[n * HD + d1];
        const __half* base = g_qkvh + (size_t)n * (3 * DMODEL) + h * HD;
        int dp0 = (d0 < 32) ? d0 + 32 : d0 - 32;
        int dp1 = (d1 < 32) ? d1 + 32 : d1 - 32;
        float sgn = (d0 < 32) ? -1.f : 1.f;

        float q0 = (__half2float(base[d0]) * c0 + sgn * __half2float(base[dp0]) * s0)
                   * (QK_SCALE * LOG2E);
        float q1 = (__half2float(base[d1]) * c1 + sgn * __half2float(base[dp1]) * s1)
                   * (QK_SCALE * LOG2E);
        float k0 = __half2float(base[DMODEL + d0]) * c0
                 + sgn * __half2float(base[DMODEL + dp0]) * s0;
        float k1 = __half2float(base[DMODEL + d1]) * c1
                 + sgn * __half2float(base[DMODEL + dp1]) * s1;

        size_t o = ((size_t)h * N_TOK + n) * 32 + wperm(w);
        ((__half2*)g_q)[o] = __floats2half2_rn(q0, q1);
        ((__half2*)g_k)[o] = __floats2half2_rn(k0, k1);
    } else {
        int b = bx - ROPE_BLOCKS;
        int h = b / (N_TOK / 64);
        int nb = b % (N_TOK / 64);
#pragma unroll
        for (int i = 0; i < 8; i++) {
            int id = tid + i * 256;
            int nl = id >> 5, wd = id & 31;
            __half2 v = *(const __half2*)(g_qkvh
                + (size_t)(nb * 64 + nl) * (3 * DMODEL) + 2 * DMODEL + h * HD + 2 * wd);
            *(__half2*)&smv[nl][2 * wd] = v;
        }
        __syncthreads();
#pragma unroll
        for (int i = 0; i < 8; i++) {
            int id = tid + i * 256;
            int dl = id >> 5, wl = id & 31;
            __half2 v = __halves2half2(smv[2 * wl][dl], smv[2 * wl + 1][dl]);
            ((__half2*)g_vt)[((size_t)(h * HD + dl)) * (N_TOK / 2) + nb * 32 + wperm(wl)] = v;
        }
    }
}

// ---------------------------------------------------------------------------
// online softmax update for one row-group (cols c0,c1 of the C fragments)
// ---------------------------------------------------------------------------
__device__ __forceinline__ void softmax_rows(float (&s)[8][4], int c0, int c1,
                                             float& m, float& l, float (&o)[8][4])
{
    float mt = -1e30f;
#pragma unroll
    for (int nt = 0; nt < 8; nt++) mt = fmaxf(mt, fmaxf(s[nt][c0], s[nt][c1]));
    mt = fmaxf(mt, __shfl_xor_sync(0xffffffffu, mt, 1));
    mt = fmaxf(mt, __shfl_xor_sync(0xffffffffu, mt, 2));
    float nm = fmaxf(m, mt);
    float al = ex2(m - nm);
    m = nm;
    float rs = 0.f;
#pragma unroll
    for (int nt = 0; nt < 8; nt++) {
        s[nt][c0] = ex2(s[nt][c0] - nm);
        s[nt][c1] = ex2(s[nt][c1] - nm);
        rs += s[nt][c0] + s[nt][c1];
    }
    rs += __shfl_xor_sync(0xffffffffu, rs, 1);
    rs += __shfl_xor_sync(0xffffffffu, rs, 2);
    l = l * al + rs;
#pragma unroll
    for (int nt = 0; nt < 8; nt++) { o[nt][c0] *= al; o[nt][c1] *= al; }
}

// ---------------------------------------------------------------------------
// Flash attention, uneven 3-way split-K (22/21/21 of 64 key-tiles),
// fp16 m16n8k16, 32 rows/warp, 256 queries/CTA, cp.async 2-buf 64-key tiles.
// Last-arriving CTA of each (qb,h) triple combines partials -> g_att.
// ---------------------------------------------------------------------------
#define KT 64
#define SW 40
#define QROWS 256
#define QBUF (QROWS * SW)
#define KBUF (KT * SW)
#define ATTN_SMEM ((QBUF + 2 * KBUF + 2 * KBUF) * 4)

__global__ void __launch_bounds__(256, 1) attn_mma()
{
    extern __shared__ uint32_t sm[];
    uint32_t* Qs = sm;
    uint32_t* Ks = Qs + QBUF;
    uint32_t* Vs = Ks + 2 * KBUF;

    const int h = blockIdx.y;
    const int qb = blockIdx.x;
    const int sp = blockIdx.z;
    const int tid = threadIdx.x;
    const int lane = tid & 31;
    const int w = tid >> 5;
    const int q4 = lane & 3;

    // uneven split: sp0 -> tiles [0,22), sp1 -> [22,43), sp2 -> [43,64)
    const int t0 = (sp == 0) ? 0 : (22 + 21 * (sp - 1));
    const int ntl = (sp == 0) ? 22 : 21;

    const __half* qg = g_q + ((size_t)h * N_TOK + (size_t)qb * QROWS) * HD;
    const __half* kg = g_k + (size_t)h * N_TOK * HD;
    const __half* vtg = g_vt + (size_t)h * HD * N_TOK;

    const uint32_t ks_u32 = (uint32_t)__cvta_generic_to_shared(Ks);
    const uint32_t vs_u32 = (uint32_t)__cvta_generic_to_shared(Vs);

#pragma unroll
    for (int i = 0; i < 8; i++) {
        int id = tid + i * 256;
        int r = id >> 3, wc = (id & 7) * 4;
        *(uint4*)&Qs[r * SW + wc] = *(const uint4*)(qg + (size_t)r * HD + wc * 2);
    }

#pragma unroll
    for (int t = 0; t < 2; t++) {
        int tt = t0 + t;
#pragma unroll
        for (int i = 0; i < 2; i++) {
            int id = tid + i * 256;
            int r = id >> 3, c8 = (id & 7) * 8;
            cp16(ks_u32 + (uint32_t)(t * KBUF + r * SW + (id & 7) * 4) * 4,
                 kg + ((size_t)tt * KT + r) * HD + c8);
            cp16(vs_u32 + (uint32_t)(t * KBUF + r * SW + (id & 7) * 4) * 4,
                 vtg + (size_t)r * N_TOK + tt * KT + c8);
        }
        CP_COMMIT();
    }

    float o0[8][4], o1[8][4];
#pragma unroll
    for (int nt = 0; nt < 8; nt++)
#pragma unroll
        for (int c = 0; c < 4; c++) { o0[nt][c] = 0.f; o1[nt][c] = 0.f; }
    float m00 = -1e30f, m01 = -1e30f, m10 = -1e30f, m11 = -1e30f;
    float l00 = 0.f, l01 = 0.f, l10 = 0.f, l11 = 0.f;

    const int qrow = w * 32 + (lane >> 2);

    for (int t = 0; t < ntl; t++) {
        CP_WAIT(1);
        __syncthreads();
        const uint32_t* Kb = Ks + (t & 1) * KBUF;
        const uint32_t* Vb = Vs + (t & 1) * KBUF;

        float s0[8][4], s1[8][4];
#pragma unroll
        for (int nt = 0; nt < 8; nt++)
#pragma unroll
            for (int c = 0; c < 4; c++) { s0[nt][c] = 0.f; s1[nt][c] = 0.f; }

#pragma unroll
        for (int ks = 0; ks < 4; ks++) {
            const int wc = ks * 8 + 2 * q4;
            uint2 aA0 = *(const uint2*)&Qs[qrow * SW + wc];
            uint2 aB0 = *(const uint2*)&Qs[(qrow + 8) * SW + wc];
            uint2 aA1 = *(const uint2*)&Qs[(qrow + 16) * SW + wc];
            uint2 aB1 = *(const uint2*)&Qs[(qrow + 24) * SW + wc];
#pragma unroll
            for (int nt = 0; nt < 8; nt++) {
                int nn = nt * 8 + (lane >> 2);
                uint2 b = *(const uint2*)&Kb[nn * SW + wc];
                mma_fp16(s0[nt][0], s0[nt][1], s0[nt][2], s0[nt][3],
                         aA0.x, aB0.x, aA0.y, aB0.y, b.x, b.y);
                mma_fp16(s1[nt][0], s1[nt][1], s1[nt][2], s1[nt][3],
                         aA1.x, aB1.x, aA1.y, aB1.y, b.x, b.y);
            }
        }

        softmax_rows(s0, 0, 1, m00, l00, o0);
        softmax_rows(s0, 2, 3, m01, l01, o0);
        softmax_rows(s1, 0, 1, m10, l10, o1);
        softmax_rows(s1, 2, 3, m11, l11, o1);

#pragma unroll
        for (int kgi = 0; kgi < 4; kgi++) {
            const int wc = kgi * 8 + 2 * q4;
            uint2 b[8];
#pragma unroll
            for (int nt = 0; nt < 8; nt++)
                b[nt] = *(const uint2*)&Vb[(nt * 8 + (lane >> 2)) * SW + wc];

            uint32_t a0 = pack2(s0[2 * kgi][0], s0[2 * kgi][1]);
            uint32_t a1 = pack2(s0[2 * kgi][2], s0[2 * kgi][3]);
            uint32_t a2 = pack2(s0[2 * kgi + 1][0], s0[2 * kgi + 1][1]);
            uint32_t a3 = pack2(s0[2 * kgi + 1][2], s0[2 * kgi + 1][3]);
#pragma unroll
            for (int nt = 0; nt < 8; nt++)
                mma_fp16(o0[nt][0], o0[nt][1], o0[nt][2], o0[nt][3],
                         a0, a1, a2, a3, b[nt].x, b[nt].y);

            a0 = pack2(s1[2 * kgi][0], s1[2 * kgi][1]);
            a1 = pack2(s1[2 * kgi][2], s1[2 * kgi][3]);
            a2 = pack2(s1[2 * kgi + 1][0], s1[2 * kgi + 1][1]);
            a3 = pack2(s1[2 * kgi + 1][2], s1[2 * kgi + 1][3]);
#pragma unroll
            for (int nt = 0; nt < 8; nt++)
                mma_fp16(o1[nt][0], o1[nt][1], o1[nt][2], o1[nt][3],
                         a0, a1, a2, a3, b[nt].x, b[nt].y);
        }

        __syncthreads();
        if (t + 2 < ntl) {
            int tt = t0 + t + 2;
            int buf = (t + 2) & 1;
#pragma unroll
            for (int i = 0; i < 2; i++) {
                int id = tid + i * 256;
                int r = id >> 3, c8 = (id & 7) * 8;
                cp16(ks_u32 + (uint32_t)(buf * KBUF + r * SW + (id & 7) * 4) * 4,
                     kg + ((size_t)tt * KT + r) * HD + c8);
                cp16(vs_u32 + (uint32_t)(buf * KBUF + r * SW + (id & 7) * 4) * 4,
                     vtg + (size_t)r * N_TOK + tt * KT + c8);
            }
        }
        CP_COMMIT();
    }

    // ---- write unnormalized partials + (m, l)
    float* po = g_po + ((size_t)(sp * NH + h) * N_TOK) * HD;
    int row0 = qb * QROWS + qrow;
#pragma unroll
    for (int nt = 0; nt < 8; nt++) {
        int dd = nt * 8 + 2 * q4;
        *(float2*)(po + (size_t)row0 * HD + dd) = make_float2(o0[nt][0], o0[nt][1]);
        *(float2*)(po + (size_t)(row0 + 8) * HD + dd) = make_float2(o0[nt][2], o0[nt][3]);
        *(float2*)(po + (size_t)(row0 + 16) * HD + dd) = make_float2(o1[nt][0], o1[nt][1]);
        *(float2*)(po + (size_t)(row0 + 24) * HD + dd) = make_float2(o1[nt][2], o1[nt][3]);
    }
    if (q4 == 0) {
        size_t mb = (size_t)(sp * NH + h) * N_TOK;
        g_pm[mb + row0] = m00;       g_pl[mb + row0] = l00;
        g_pm[mb + row0 + 8] = m01;   g_pl[mb + row0 + 8] = l01;
        g_pm[mb + row0 + 16] = m10;  g_pl[mb + row0 + 16] = l10;
        g_pm[mb + row0 + 24] = m11;  g_pl[mb + row0 + 24] = l11;
    }

    // ---- last CTA of this (qb,h) triple combines (threadFenceReduction pattern)
    __threadfence();
    __syncthreads();
    __shared__ int s_last;
    if (tid == 0) {
        int prev = atomicAdd(&g_ctr[qb * NH + h], 1);
        s_last = ((prev % NSPLIT) == NSPLIT - 1);
    }
    __syncthreads();
    if (!s_last) return;
    __threadfence();   // acquire: partner partials visible

#pragma unroll
    for (int g = 0; g < 4; g++) {
        int r = row0 + g * 8;
        float m[NSPLIT], l[NSPLIT];
        float ms = -1e30f;
#pragma unroll
        for (int s = 0; s < NSPLIT; s++) {
            size_t mb = (size_t)(s * NH + h) * N_TOK + r;
            m[s] = g_pm[mb];
            l[s] = g_pl[mb];
            ms = fmaxf(ms, m[s]);
        }
        float wgt[NSPLIT], denom = 0.f;
#pragma unroll
        for (int s = 0; s < NSPLIT; s++) {
            wgt[s] = ex2(m[s] - ms);
            denom += l[s] * wgt[s];
        }
        float inv = 1.f / denom;
#pragma unroll
        for (int s = 0; s < NSPLIT; s++) wgt[s] *= inv;

#pragma unroll
        for (int nt = 0; nt < 8; nt++) {
            int dd = nt * 8 + 2 * q4;
            float ax = 0.f, ay = 0.f;
#pragma unroll
            for (int s = 0; s < NSPLIT; s++) {
                float2 O = *(const float2*)(g_po
                    + ((size_t)(s * NH + h) * N_TOK + r) * HD + dd);
                ax += O.x * wgt[s];
                ay += O.y * wgt[s];
            }
            int Wp = wperm(h * 32 + nt * 4 + q4);
            ((__half2*)g_att)[(size_t)r * (DMODEL / 2) + Wp] = __floats2half2_rn(ax, ay);
        }
    }
}

// ---------------------------------------------------------------------------
extern "C" void kernel_launch(void* const* d_in, const int* in_sizes, int n_in,
                              void* d_out, int out_size)
{
    (void)in_sizes; (void)n_in; (void)out_size;
    const float* hs     = (const float*)d_in[0];
    const float* cosp   = (const float*)d_in[1];
    const float* sinp   = (const float*)d_in[2];
    const float* qkv_w  = (const float*)d_in[3];
    const float* qkv_b  = (const float*)d_in[4];
    const float* proj_w = (const float*)d_in[5];
    const float* proj_b = (const float*)d_in[6];
    float* out = (float*)d_out;

    void *p_qkvh = nullptr, *p_att = nullptr, *p_hs = nullptr, *p_w1t = nullptr, *p_w2t = nullptr;
    cudaGetSymbolAddress(&p_qkvh, g_qkvh);
    cudaGetSymbolAddress(&p_att, g_att);
    cudaGetSymbolAddress(&p_hs, g_hs);
    cudaGetSymbolAddress(&p_w1t, g_w1t);
    cudaGetSymbolAddress(&p_w2t, g_w2t);

    static bool init_done = false;
    static cudaStream_t s2;
    static cudaEvent_t ev0, ev1, ev2;
    if (!init_done) {
        cudaFuncSetAttribute(attn_mma, cudaFuncAttributeMaxDynamicSharedMemorySize, ATTN_SMEM);
        cudaFuncSetAttribute(gemm_fp16<0>, cudaFuncAttributeMaxDynamicSharedMemorySize, GEMM_SMEM);
        cudaFuncSetAttribute(gemm_fp16<1>, cudaFuncAttributeMaxDynamicSharedMemorySize, GEMM_SMEM);
        cudaStreamCreateWithFlags(&s2, cudaStreamNonBlocking);
        cudaEventCreateWithFlags(&ev0, cudaEventDisableTiming);
        cudaEventCreateWithFlags(&ev1, cudaEventDisableTiming);
        cudaEventCreateWithFlags(&ev2, cudaEventDisableTiming);
        init_done = true;
    }

    // fork: weight transposes on s2, concurrent with convert_hs / GEMM1
    cudaEventRecord(ev0, 0);
    cudaStreamWaitEvent(s2, ev0, 0);
    transpose_w<<<dim3(3 * DMODEL / 64, DMODEL / 64), 256, 0, s2>>>(
        qkv_w, (__half*)p_w1t, DMODEL, 3 * DMODEL);
    cudaEventRecord(ev1, s2);
    transpose_w<<<dim3(DMODEL / 64, DMODEL / 64), 256, 0, s2>>>(
        proj_w, (__half*)p_w2t, DMODEL, DMODEL);
    cudaEventRecord(ev2, s2);

    // main: hs -> fp16 (word-permuted)
    convert_hs<<<(N_TOK * DMODEL / 2 + 255) / 256, 256>>>(hs);

    // 1) QKV = hs @ qkv_w + qkv_b  (fp16 out, canonical)
    cudaStreamWaitEvent(0, ev1, 0);
    gemm_fp16<1><<<dim3(3 * DMODEL / 128, N_TOK / 128), 256, GEMM_SMEM>>>(
        (const __half*)p_hs, (const __half*)p_w1t, qkv_b, p_qkvh,
        N_TOK, 3 * DMODEL, DMODEL);

    // 2) fused RoPE+split + V transpose
    qkv_post<<<ROPE_BLOCKS + VT_BLOCKS, 256>>>(cosp, sinp);

    // 3) Flash attention, uneven 3-way split-K, fused last-CTA combine
    attn_mma<<<dim3(N_TOK / QROWS, NH, NSPLIT), 256, ATTN_SMEM>>>();

    // 4) out = att @ proj_w + proj_b  (fp32 out)
    cudaStreamWaitEvent(0, ev2, 0);
    gemm_fp16<0><<<dim3(DMODEL / 128, N_TOK / 128), 256, GEMM_SMEM>>>(
        (const __half*)p_att, (const __half*)p_w2t, proj_b, out,
        N_TOK, DMODEL, DMODEL);
}

// round 15
// speedup vs baseline: 1.1068x; 1.1068x over previous
#include <cuda_runtime.h>
#include <cuda_fp16.h>
#include <cstdint>

#define N_TOK 4096
#define NH 12
#define HD 64
#define DMODEL 768
#define QK_SCALE 0.125f
#define LOG2E 1.4426950408889634f
#define NSPLIT 3

// Scratch (device globals: allocation-free per harness rules)
__device__ __half g_qkvh[(size_t)N_TOK * 3 * DMODEL]; // fp16 qkv [n][3D] canonical
__device__ __half g_hs[(size_t)N_TOK * DMODEL];        // fp16 hidden_states, word-permuted k
__device__ __half g_w1t[(size_t)3 * DMODEL * DMODEL];  // fp16 qkv_w^T [n][k], word-permuted k
__device__ __half g_w2t[(size_t)DMODEL * DMODEL];      // fp16 proj_w^T [n][k], word-permuted k
__device__ __half g_q[(size_t)NH * N_TOK * HD];        // [h][n][d-perm], *scale*log2e
__device__ __half g_k[(size_t)NH * N_TOK * HD];        // [h][n][d-perm]
__device__ __half g_vt[(size_t)NH * HD * N_TOK];       // [h][d][key-perm] V^T
__device__ __half g_att[(size_t)N_TOK * DMODEL];       // attn out [n][h*HD+d], word-permuted
// split-K partials
__device__ float g_po[(size_t)NSPLIT * NH * N_TOK * HD];
__device__ float g_pm[(size_t)NSPLIT * NH * N_TOK];
__device__ float g_pl[(size_t)NSPLIT * NH * N_TOK];

// ---------------------------------------------------------------------------
// helpers
// ---------------------------------------------------------------------------
__device__ __forceinline__ float ex2(float x) {
    float y;
    asm("ex2.approx.f32 %0, %1;" : "=f"(y) : "f"(x));
    return y;
}
__device__ __forceinline__ void mma_fp16(float& c0, float& c1, float& c2, float& c3,
                                         uint32_t a0, uint32_t a1, uint32_t a2, uint32_t a3,
                                         uint32_t b0, uint32_t b1) {
    asm volatile(
        "mma.sync.aligned.m16n8k16.row.col.f32.f16.f16.f32 "
        "{%0,%1,%2,%3}, {%4,%5,%6,%7}, {%8,%9}, {%0,%1,%2,%3};\n"
        : "+f"(c0), "+f"(c1), "+f"(c2), "+f"(c3)
        : "r"(a0), "r"(a1), "r"(a2), "r"(a3), "r"(b0), "r"(b1));
}
__device__ __forceinline__ void cp16(uint32_t dst, const void* src) {
    asm volatile("cp.async.cg.shared.global [%0], [%1], 16;" :: "r"(dst), "l"(src));
}
#define CP_COMMIT() asm volatile("cp.async.commit_group;")
#define CP_WAIT(n)  asm volatile("cp.async.wait_group %0;" :: "n"(n))

// pair-interleave permutation on 32-bit words within each 8-word group
__device__ __forceinline__ int wperm(int w) {
    int r = w & 7;
    return (w & ~7) | ((r < 4) ? (2 * r) : (2 * (r - 4) + 1));
}
__device__ __forceinline__ uint32_t pack2(float lo, float hi) {
    __half2 h = __floats2half2_rn(lo, hi);
    return *reinterpret_cast<uint32_t*>(&h);
}

// ---------------------------------------------------------------------------
// prep: hs -> fp16 (word-permuted) AND both weight transposes, one kernel.
// Blocks: [0, HS_B): convert_hs; [HS_B, +W1_B): w1^T; then w2^T.
// ---------------------------------------------------------------------------
#define HS_B (N_TOK * DMODEL / 2 / 256)        // 6144
#define W1_B ((3 * DMODEL / 64) * (DMODEL / 64))  // 36*12 = 432
#define W2_B ((DMODEL / 64) * (DMODEL / 64))      // 144

__global__ void __launch_bounds__(256) prep(const float* __restrict__ hs,
                                            const float* __restrict__ w1,
                                            const float* __restrict__ w2)
{
    __shared__ float sm[64][65];
    const int bx = blockIdx.x;
    const int tid = threadIdx.x;

    if (bx < HS_B) {
        int i = bx * 256 + tid;
        int row = i / (DMODEL / 2);
        int w = i % (DMODEL / 2);
        float2 v = *(const float2*)(hs + (size_t)row * DMODEL + w * 2);
        ((__half2*)g_hs)[(size_t)row * (DMODEL / 2) + wperm(w)] = __floats2half2_rn(v.x, v.y);
        return;
    }

    const float* W;
    __half* WT;
    int n0, k0, N;
    if (bx < HS_B + W1_B) {
        int b = bx - HS_B;
        W = w1; WT = g_w1t; N = 3 * DMODEL;
        n0 = (b % 36) * 64; k0 = (b / 36) * 64;
    } else {
        int b = bx - HS_B - W1_B;
        W = w2; WT = g_w2t; N = DMODEL;
        n0 = (b % 12) * 64; k0 = (b / 12) * 64;
    }
#pragma unroll
    for (int i = 0; i < 16; i++) {
        int id = tid + i * 256;
        int kl = id >> 6, nl = id & 63;
        sm[kl][nl] = W[(size_t)(k0 + kl) * N + n0 + nl];
    }
    __syncthreads();
#pragma unroll
    for (int i = 0; i < 8; i++) {
        int id = tid + i * 256;
        int nl = id >> 5, wl = id & 31;
        int kl = wl * 2;
        __half2 v = __floats2half2_rn(sm[kl][nl], sm[kl + 1][nl]);
        int Wg = (k0 >> 1) + wl;
        ((__half2*)WT)[(size_t)(n0 + nl) * (DMODEL >> 1) + wperm(Wg)] = v;
    }
}

// ---------------------------------------------------------------------------
// fp16 GEMM: C[M,Nc] = A[M,K] @ BT[Nc,K]^T + bias. by0 = row-tile offset.
// A,BT fp16 word-permuted k. 128x128x64 tiles, 256 thr, 2 CTA/SM, cp.async 2-buf.
// ---------------------------------------------------------------------------
#define AW 40
#define ABUF (128 * AW)
#define GEMM_SMEM (4 * ABUF * 4)

template <int HALF_OUT>
__global__ void __launch_bounds__(256, 2) gemm_fp16(
    const __half* __restrict__ A, const __half* __restrict__ BT,
    const float* __restrict__ bias, void* __restrict__ Cv,
    int M, int Nc, int K, int by0)
{
    extern __shared__ uint32_t smg[];
    uint32_t* As = smg;
    uint32_t* Bs = smg + 2 * ABUF;

    const int tid = threadIdx.x;
    const int lane = tid & 31;
    const int w = tid >> 5;
    const int wm = w >> 2, wn = w & 3;
    const int q4 = lane & 3;
    const int bx = blockIdx.x, by = blockIdx.y + by0;

    const __half* Ag = A + (size_t)(by * 128) * K;
    const __half* Bg = BT + (size_t)(bx * 128) * K;

    const uint32_t as_u = (uint32_t)__cvta_generic_to_shared(As);
    const uint32_t bs_u = (uint32_t)__cvta_generic_to_shared(Bs);

    float acc[4][4][4];
#pragma unroll
    for (int mt = 0; mt < 4; mt++)
#pragma unroll
        for (int nt = 0; nt < 4; nt++)
#pragma unroll
            for (int c = 0; c < 4; c++) acc[mt][nt][c] = 0.f;

    const int NC = K / 64;

#pragma unroll
    for (int i = 0; i < 4; i++) {
        int id = tid + i * 256;
        int r = id >> 3, c8 = (id & 7) * 8;
        cp16(as_u + (uint32_t)(r * AW + (id & 7) * 4) * 4, Ag + (size_t)r * K + c8);
        cp16(bs_u + (uint32_t)(r * AW + (id & 7) * 4) * 4, Bg + (size_t)r * K + c8);
    }
    CP_COMMIT();

    for (int ch = 0; ch < NC; ch++) {
        if (ch + 1 < NC) {
            int k0 = (ch + 1) * 64;
            int buf = (ch + 1) & 1;
#pragma unroll
            for (int i = 0; i < 4; i++) {
                int id = tid + i * 256;
                int r = id >> 3, c8 = (id & 7) * 8;
                cp16(as_u + (uint32_t)(buf * ABUF + r * AW + (id & 7) * 4) * 4,
                     Ag + (size_t)r * K + k0 + c8);
                cp16(bs_u + (uint32_t)(buf * ABUF + r * AW + (id & 7) * 4) * 4,
                     Bg + (size_t)r * K + k0 + c8);
            }
        }
        CP_COMMIT();
        CP_WAIT(1);
        __syncthreads();

        const uint32_t* Ab = As + (ch & 1) * ABUF;
        const uint32_t* Bb = Bs + (ch & 1) * ABUF;

#pragma unroll
        for (int ks = 0; ks < 4; ks++) {
            const int wc = ks * 8 + 2 * q4;
            uint2 a[4][2];
#pragma unroll
            for (int mt = 0; mt < 4; mt++) {
                int r = wm * 64 + mt * 16 + (lane >> 2);
                a[mt][0] = *(const uint2*)&Ab[r * AW + wc];
                a[mt][1] = *(const uint2*)&Ab[(r + 8) * AW + wc];
            }
            uint2 b[4];
#pragma unroll
            for (int nt = 0; nt < 4; nt++) {
                int n = wn * 32 + nt * 8 + (lane >> 2);
                b[nt] = *(const uint2*)&Bb[n * AW + wc];
            }
#pragma unroll
            for (int mt = 0; mt < 4; mt++)
#pragma unroll
                for (int nt = 0; nt < 4; nt++)
                    mma_fp16(acc[mt][nt][0], acc[mt][nt][1], acc[mt][nt][2], acc[mt][nt][3],
                             a[mt][0].x, a[mt][1].x, a[mt][0].y, a[mt][1].y,
                             b[nt].x, b[nt].y);
        }
        __syncthreads();
    }

#pragma unroll
    for (int mt = 0; mt < 4; mt++) {
#pragma unroll
        for (int nt = 0; nt < 4; nt++) {
            int r = by * 128 + wm * 64 + mt * 16 + (lane >> 2);
            int cn = bx * 128 + wn * 32 + nt * 8 + 2 * q4;
            float b0 = bias[cn], b1 = bias[cn + 1];
            if (HALF_OUT) {
                __half* C = (__half*)Cv;
                *(__half2*)(C + (size_t)r * Nc + cn) =
                    __floats2half2_rn(acc[mt][nt][0] + b0, acc[mt][nt][1] + b1);
                *(__half2*)(C + (size_t)(r + 8) * Nc + cn) =
                    __floats2half2_rn(acc[mt][nt][2] + b0, acc[mt][nt][3] + b1);
            } else {
                float* C = (float*)Cv;
                *(float2*)(C + (size_t)r * Nc + cn) =
                    make_float2(acc[mt][nt][0] + b0, acc[mt][nt][1] + b1);
                *(float2*)(C + (size_t)(r + 8) * Nc + cn) =
                    make_float2(acc[mt][nt][2] + b0, acc[mt][nt][3] + b1);
            }
        }
    }
}

// ---------------------------------------------------------------------------
// Fused post-QKV over a 2048-token half: RoPE+split q/k AND V transpose.
// n_half = 0 or 1.
// ---------------------------------------------------------------------------
#define HTOK (N_TOK / 2)                        // 2048
#define ROPE_BH (HTOK * NH * 32 / 256)          // 3072
#define VT_BH ((HTOK / 64) * NH)                // 384

__global__ void __launch_bounds__(256) qkv_post(const float* __restrict__ cosp,
                                                const float* __restrict__ sinp,
                                                int n_half)
{
    __shared__ __half smv[64][72];
    const int bx = blockIdx.x;
    const int tid = threadIdx.x;
    const int n_off = n_half * HTOK;

    if (bx < ROPE_BH) {
        int idx = bx * 256 + tid;
        int w = idx & 31;
        int h = (idx >> 5) % NH;
        int n = n_off + idx / (NH * 32);
        int d0 = 2 * w, d1 = 2 * w + 1;

        float c0 = cosp[n * HD + d0], c1 = cosp[n * HD + d1];
        float s0 = sinp[n * HD + d0], s1 = sinp[n * HD + d1];
        const __half* base = g_qkvh + (size_t)n * (3 * DMODEL) + h * HD;
        int dp0 = (d0 < 32) ? d0 + 32 : d0 - 32;
        int dp1 = (d1 < 32) ? d1 + 32 : d1 - 32;
        float sgn = (d0 < 32) ? -1.f : 1.f;

        float q0 = (__half2float(base[d0]) * c0 + sgn * __half2float(base[dp0]) * s0)
                   * (QK_SCALE * LOG2E);
        float q1 = (__half2float(base[d1]) * c1 + sgn * __half2float(base[dp1]) * s1)
                   * (QK_SCALE * LOG2E);
        float k0 = __half2float(base[DMODEL + d0]) * c0
                 + sgn * __half2float(base[DMODEL + dp0]) * s0;
        float k1 = __half2float(base[DMODEL + d1]) * c1
                 + sgn * __half2float(base[DMODEL + dp1]) * s1;

        size_t o = ((size_t)h * N_TOK + n) * 32 + wperm(w);
        ((__half2*)g_q)[o] = __floats2half2_rn(q0, q1);
        ((__half2*)g_k)[o] = __floats2half2_rn(k0, k1);
    } else {
        int b = bx - ROPE_BH;
        int h = b / (HTOK / 64);
        int nb = n_off / 64 + b % (HTOK / 64);
#pragma unroll
        for (int i = 0; i < 8; i++) {
            int id = tid + i * 256;
            int nl = id >> 5, wd = id & 31;
            __half2 v = *(const __half2*)(g_qkvh
                + (size_t)(nb * 64 + nl) * (3 * DMODEL) + 2 * DMODEL + h * HD + 2 * wd);
            *(__half2*)&smv[nl][2 * wd] = v;
        }
        __syncthreads();
#pragma unroll
        for (int i = 0; i < 8; i++) {
            int id = tid + i * 256;
            int dl = id >> 5, wl = id & 31;
            __half2 v = __halves2half2(smv[2 * wl][dl], smv[2 * wl + 1][dl]);
            ((__half2*)g_vt)[((size_t)(h * HD + dl)) * (N_TOK / 2) + nb * 32 + wperm(wl)] = v;
        }
    }
}

// ---------------------------------------------------------------------------
// online softmax update for one row-group (cols c0,c1 of the C fragments)
// ---------------------------------------------------------------------------
__device__ __forceinline__ void softmax_rows(float (&s)[8][4], int c0, int c1,
                                             float& m, float& l, float (&o)[8][4])
{
    float mt = -1e30f;
#pragma unroll
    for (int nt = 0; nt < 8; nt++) mt = fmaxf(mt, fmaxf(s[nt][c0], s[nt][c1]));
    mt = fmaxf(mt, __shfl_xor_sync(0xffffffffu, mt, 1));
    mt = fmaxf(mt, __shfl_xor_sync(0xffffffffu, mt, 2));
    float nm = fmaxf(m, mt);
    float al = ex2(m - nm);
    m = nm;
    float rs = 0.f;
#pragma unroll
    for (int nt = 0; nt < 8; nt++) {
        s[nt][c0] = ex2(s[nt][c0] - nm);
        s[nt][c1] = ex2(s[nt][c1] - nm);
        rs += s[nt][c0] + s[nt][c1];
    }
    rs += __shfl_xor_sync(0xffffffffu, rs, 1);
    rs += __shfl_xor_sync(0xffffffffu, rs, 2);
    l = l * al + rs;
#pragma unroll
    for (int nt = 0; nt < 8; nt++) { o[nt][c0] *= al; o[nt][c1] *= al; }
}

// ---------------------------------------------------------------------------
// Flash attention, uneven 3-way split-K (22/21/21 of 64 key-tiles),
// fp16 m16n8k16, 32 rows/warp, 256 queries/CTA, cp.async 2-buf 64-key tiles.
// ---------------------------------------------------------------------------
#define KT 64
#define SW 40
#define QROWS 256
#define QBUF (QROWS * SW)
#define KBUF (KT * SW)
#define ATTN_SMEM ((QBUF + 2 * KBUF + 2 * KBUF) * 4)

__global__ void __launch_bounds__(256, 1) attn_mma()
{
    extern __shared__ uint32_t sm[];
    uint32_t* Qs = sm;
    uint32_t* Ks = Qs + QBUF;
    uint32_t* Vs = Ks + 2 * KBUF;

    const int h = blockIdx.y;
    const int qb = blockIdx.x;
    const int sp = blockIdx.z;
    const int tid = threadIdx.x;
    const int lane = tid & 31;
    const int w = tid >> 5;
    const int q4 = lane & 3;

    const int t0 = (sp == 0) ? 0 : (22 + 21 * (sp - 1));
    const int ntl = (sp == 0) ? 22 : 21;

    const __half* qg = g_q + ((size_t)h * N_TOK + (size_t)qb * QROWS) * HD;
    const __half* kg = g_k + (size_t)h * N_TOK * HD;
    const __half* vtg = g_vt + (size_t)h * HD * N_TOK;

    const uint32_t ks_u32 = (uint32_t)__cvta_generic_to_shared(Ks);
    const uint32_t vs_u32 = (uint32_t)__cvta_generic_to_shared(Vs);

#pragma unroll
    for (int i = 0; i < 8; i++) {
        int id = tid + i * 256;
        int r = id >> 3, wc = (id & 7) * 4;
        *(uint4*)&Qs[r * SW + wc] = *(const uint4*)(qg + (size_t)r * HD + wc * 2);
    }

#pragma unroll
    for (int t = 0; t < 2; t++) {
        int tt = t0 + t;
#pragma unroll
        for (int i = 0; i < 2; i++) {
            int id = tid + i * 256;
            int r = id >> 3, c8 = (id & 7) * 8;
            cp16(ks_u32 + (uint32_t)(t * KBUF + r * SW + (id & 7) * 4) * 4,
                 kg + ((size_t)tt * KT + r) * HD + c8);
            cp16(vs_u32 + (uint32_t)(t * KBUF + r * SW + (id & 7) * 4) * 4,
                 vtg + (size_t)r * N_TOK + tt * KT + c8);
        }
        CP_COMMIT();
    }

    float o0[8][4], o1[8][4];
#pragma unroll
    for (int nt = 0; nt < 8; nt++)
#pragma unroll
        for (int c = 0; c < 4; c++) { o0[nt][c] = 0.f; o1[nt][c] = 0.f; }
    float m00 = -1e30f, m01 = -1e30f, m10 = -1e30f, m11 = -1e30f;
    float l00 = 0.f, l01 = 0.f, l10 = 0.f, l11 = 0.f;

    const int qrow = w * 32 + (lane >> 2);

    for (int t = 0; t < ntl; t++) {
        CP_WAIT(1);
        __syncthreads();
        const uint32_t* Kb = Ks + (t & 1) * KBUF;
        const uint32_t* Vb = Vs + (t & 1) * KBUF;

        float s0[8][4], s1[8][4];
#pragma unroll
        for (int nt = 0; nt < 8; nt++)
#pragma unroll
            for (int c = 0; c < 4; c++) { s0[nt][c] = 0.f; s1[nt][c] = 0.f; }

#pragma unroll
        for (int ks = 0; ks < 4; ks++) {
            const int wc = ks * 8 + 2 * q4;
            uint2 aA0 = *(const uint2*)&Qs[qrow * SW + wc];
            uint2 aB0 = *(const uint2*)&Qs[(qrow + 8) * SW + wc];
            uint2 aA1 = *(const uint2*)&Qs[(qrow + 16) * SW + wc];
            uint2 aB1 = *(const uint2*)&Qs[(qrow + 24) * SW + wc];
#pragma unroll
            for (int nt = 0; nt < 8; nt++) {
                int nn = nt * 8 + (lane >> 2);
                uint2 b = *(const uint2*)&Kb[nn * SW + wc];
                mma_fp16(s0[nt][0], s0[nt][1], s0[nt][2], s0[nt][3],
                         aA0.x, aB0.x, aA0.y, aB0.y, b.x, b.y);
                mma_fp16(s1[nt][0], s1[nt][1], s1[nt][2], s1[nt][3],
                         aA1.x, aB1.x, aA1.y, aB1.y, b.x, b.y);
            }
        }

        softmax_rows(s0, 0, 1, m00, l00, o0);
        softmax_rows(s0, 2, 3, m01, l01, o0);
        softmax_rows(s1, 0, 1, m10, l10, o1);
        softmax_rows(s1, 2, 3, m11, l11, o1);

#pragma unroll
        for (int kgi = 0; kgi < 4; kgi++) {
            const int wc = kgi * 8 + 2 * q4;
            uint2 b[8];
#pragma unroll
            for (int nt = 0; nt < 8; nt++)
                b[nt] = *(const uint2*)&Vb[(nt * 8 + (lane >> 2)) * SW + wc];

            uint32_t a0 = pack2(s0[2 * kgi][0], s0[2 * kgi][1]);
            uint32_t a1 = pack2(s0[2 * kgi][2], s0[2 * kgi][3]);
            uint32_t a2 = pack2(s0[2 * kgi + 1][0], s0[2 * kgi + 1][1]);
            uint32_t a3 = pack2(s0[2 * kgi + 1][2], s0[2 * kgi + 1][3]);
#pragma unroll
            for (int nt = 0; nt < 8; nt++)
                mma_fp16(o0[nt][0], o0[nt][1], o0[nt][2], o0[nt][3],
                         a0, a1, a2, a3, b[nt].x, b[nt].y);

            a0 = pack2(s1[2 * kgi][0], s1[2 * kgi][1]);
            a1 = pack2(s1[2 * kgi][2], s1[2 * kgi][3]);
            a2 = pack2(s1[2 * kgi + 1][0], s1[2 * kgi + 1][1]);
            a3 = pack2(s1[2 * kgi + 1][2], s1[2 * kgi + 1][3]);
#pragma unroll
            for (int nt = 0; nt < 8; nt++)
                mma_fp16(o1[nt][0], o1[nt][1], o1[nt][2], o1[nt][3],
                         a0, a1, a2, a3, b[nt].x, b[nt].y);
        }

        __syncthreads();
        if (t + 2 < ntl) {
            int tt = t0 + t + 2;
            int buf = (t + 2) & 1;
#pragma unroll
            for (int i = 0; i < 2; i++) {
                int id = tid + i * 256;
                int r = id >> 3, c8 = (id & 7) * 8;
                cp16(ks_u32 + (uint32_t)(buf * KBUF + r * SW + (id & 7) * 4) * 4,
                     kg + ((size_t)tt * KT + r) * HD + c8);
                cp16(vs_u32 + (uint32_t)(buf * KBUF + r * SW + (id & 7) * 4) * 4,
                     vtg + (size_t)r * N_TOK + tt * KT + c8);
            }
        }
        CP_COMMIT();
    }

    float* po = g_po + ((size_t)(sp * NH + h) * N_TOK) * HD;
    int row0 = qb * QROWS + qrow;
#pragma unroll
    for (int nt = 0; nt < 8; nt++) {
        int dd = nt * 8 + 2 * q4;
        *(float2*)(po + (size_t)row0 * HD + dd) = make_float2(o0[nt][0], o0[nt][1]);
        *(float2*)(po + (size_t)(row0 + 8) * HD + dd) = make_float2(o0[nt][2], o0[nt][3]);
        *(float2*)(po + (size_t)(row0 + 16) * HD + dd) = make_float2(o1[nt][0], o1[nt][1]);
        *(float2*)(po + (size_t)(row0 + 24) * HD + dd) = make_float2(o1[nt][2], o1[nt][3]);
    }
    if (q4 == 0) {
        size_t mb = (size_t)(sp * NH + h) * N_TOK;
        g_pm[mb + row0] = m00;       g_pl[mb + row0] = l00;
        g_pm[mb + row0 + 8] = m01;   g_pl[mb + row0 + 8] = l01;
        g_pm[mb + row0 + 16] = m10;  g_pl[mb + row0 + 16] = l10;
        g_pm[mb + row0 + 24] = m11;  g_pl[mb + row0 + 24] = l11;
    }
}

// ---------------------------------------------------------------------------
// 3-way split-K combine over a token half -> fp16 word-permuted g_att
// ---------------------------------------------------------------------------
__global__ void __launch_bounds__(256) attn_combine(int n_half)
{
    const int h = blockIdx.y;
    const int tid = threadIdx.x;
    const int n = n_half * HTOK + blockIdx.x * 16 + (tid >> 4);
    const int c = (tid & 15) * 4;

    size_t mb[NSPLIT];
    float m[NSPLIT], l[NSPLIT];
    float ms = -1e30f;
#pragma unroll
    for (int s = 0; s < NSPLIT; s++) {
        mb[s] = (size_t)(s * NH + h) * N_TOK + n;
        m[s] = g_pm[mb[s]];
        l[s] = g_pl[mb[s]];
        ms = fmaxf(ms, m[s]);
    }
    float wgt[NSPLIT], denom = 0.f;
#pragma unroll
    for (int s = 0; s < NSPLIT; s++) {
        wgt[s] = ex2(m[s] - ms);
        denom += l[s] * wgt[s];
    }
    float inv = 1.f / denom;

    float4 acc = make_float4(0.f, 0.f, 0.f, 0.f);
#pragma unroll
    for (int s = 0; s < NSPLIT; s++) {
        float a = wgt[s] * inv;
        float4 O = *(const float4*)(g_po + mb[s] * HD + c);
        acc.x += O.x * a; acc.y += O.y * a; acc.z += O.z * a; acc.w += O.w * a;
    }

    int W = (h * HD + c) >> 1;
    ((__half2*)g_att)[(size_t)n * (DMODEL / 2) + wperm(W)] =
        __floats2half2_rn(acc.x, acc.y);
    ((__half2*)g_att)[(size_t)n * (DMODEL / 2) + wperm(W + 1)] =
        __floats2half2_rn(acc.z, acc.w);
}

// ---------------------------------------------------------------------------
extern "C" void kernel_launch(void* const* d_in, const int* in_sizes, int n_in,
                              void* d_out, int out_size)
{
    (void)in_sizes; (void)n_in; (void)out_size;
    const float* hs     = (const float*)d_in[0];
    const float* cosp   = (const float*)d_in[1];
    const float* sinp   = (const float*)d_in[2];
    const float* qkv_w  = (const float*)d_in[3];
    const float* qkv_b  = (const float*)d_in[4];
    const float* proj_w = (const float*)d_in[5];
    const float* proj_b = (const float*)d_in[6];
    float* out = (float*)d_out;

    void *p_qkvh = nullptr, *p_att = nullptr, *p_hs = nullptr, *p_w1t = nullptr, *p_w2t = nullptr;
    cudaGetSymbolAddress(&p_qkvh, g_qkvh);
    cudaGetSymbolAddress(&p_att, g_att);
    cudaGetSymbolAddress(&p_hs, g_hs);
    cudaGetSymbolAddress(&p_w1t, g_w1t);
    cudaGetSymbolAddress(&p_w2t, g_w2t);

    static bool init_done = false;
    static cudaStream_t s2;
    static cudaEvent_t evA, evB, evC, evD;
    if (!init_done) {
        cudaFuncSetAttribute(attn_mma, cudaFuncAttributeMaxDynamicSharedMemorySize, ATTN_SMEM);
        cudaFuncSetAttribute(gemm_fp16<0>, cudaFuncAttributeMaxDynamicSharedMemorySize, GEMM_SMEM);
        cudaFuncSetAttribute(gemm_fp16<1>, cudaFuncAttributeMaxDynamicSharedMemorySize, GEMM_SMEM);
        cudaStreamCreateWithFlags(&s2, cudaStreamNonBlocking);
        cudaEventCreateWithFlags(&evA, cudaEventDisableTiming);
        cudaEventCreateWithFlags(&evB, cudaEventDisableTiming);
        cudaEventCreateWithFlags(&evC, cudaEventDisableTiming);
        cudaEventCreateWithFlags(&evD, cudaEventDisableTiming);
        init_done = true;
    }

    // 0) prep: hs->fp16 + both weight transposes (one kernel)
    prep<<<HS_B + W1_B + W2_B, 256>>>(hs, qkv_w, proj_w);

    // 1) GEMM1 row-half 0 (tokens 0..2047), fp16 out
    gemm_fp16<1><<<dim3(3 * DMODEL / 128, 16), 256, GEMM_SMEM>>>(
        (const __half*)p_hs, (const __half*)p_w1t, qkv_b, p_qkvh,
        N_TOK, 3 * DMODEL, DMODEL, 0);
    cudaEventRecord(evA, 0);

    // 1b) GEMM1 row-half 1 on main; qkv_post half 0 on s2 (overlapped)
    gemm_fp16<1><<<dim3(3 * DMODEL / 128, 16), 256, GEMM_SMEM>>>(
        (const __half*)p_hs, (const __half*)p_w1t, qkv_b, p_qkvh,
        N_TOK, 3 * DMODEL, DMODEL, 16);
    cudaStreamWaitEvent(s2, evA, 0);
    qkv_post<<<ROPE_BH + VT_BH, 256, 0, s2>>>(cosp, sinp, 0);
    cudaEventRecord(evB, s2);

    // 2) qkv_post half 1 on main (after GEMM1 half 1)
    qkv_post<<<ROPE_BH + VT_BH, 256>>>(cosp, sinp, 1);
    cudaStreamWaitEvent(0, evB, 0);

    // 3) Flash attention, uneven 3-way split-K
    attn_mma<<<dim3(N_TOK / QROWS, NH, NSPLIT), 256, ATTN_SMEM>>>();

    // 3b) combine half 0 -> GEMM2 half 0 (s2) overlapped with combine half 1
    attn_combine<<<dim3(HTOK / 16, NH), 256>>>(0);
    cudaEventRecord(evC, 0);
    attn_combine<<<dim3(HTOK / 16, NH), 256>>>(1);

    cudaStreamWaitEvent(s2, evC, 0);
    gemm_fp16<0><<<dim3(DMODEL / 128, 16), 256, GEMM_SMEM, s2>>>(
        (const __half*)p_att, (const __half*)p_w2t, proj_b, out,
        N_TOK, DMODEL, DMODEL, 0);
    cudaEventRecord(evD, s2);

    // 4) GEMM2 half 1 on main (after combine half 1); join s2
    gemm_fp16<0><<<dim3(DMODEL / 128, 16), 256, GEMM_SMEM>>>(
        (const __half*)p_att, (const __half*)p_w2t, proj_b, out,
        N_TOK, DMODEL, DMODEL, 16);
    cudaStreamWaitEvent(0, evD, 0);
}